// round 11
// baseline (speedup 1.0000x reference)
#include <cuda_runtime.h>
#include <cuda_bf16.h>
#include <cuda_fp16.h>
#include <cstdint>

#define N_NODES 50000
#define N_PAD   50048          // 391 * 128
#define R_REL   16
#define B_BASES 8
#define DIN     128
#define DOUT    128
#define NNZ     1600000
#define M_TILES 391

typedef unsigned int uint;

// Scratch: device globals (no allocation allowed)
__device__ __nv_bfloat16 g_Xh[(size_t)N_PAD * DIN];
__device__ __nv_bfloat16 g_Xl[(size_t)N_PAD * DIN];
__device__ __nv_bfloat16 g_BTh[B_BASES * DOUT * DIN];
__device__ __nv_bfloat16 g_BTl[B_BASES * DOUT * DIN];
__device__ __half g_XB[(size_t)B_BASES * N_NODES * DOUT];   // 102.4 MB (fp16)
__device__ __half g_FW[(size_t)R_REL * N_NODES * DOUT];     // 204.8 MB (fp16)
__device__ int    g_idx64;
// CSR binning scratch
__device__ int   g_cnt[N_NODES];
__device__ int   g_start[N_NODES + 1];
__device__ int   g_cursor[N_NODES];
__device__ int2  g_edge[NNZ];

// ---------------------------------------------------------------------------
__device__ __forceinline__ uint32_t smem_u32(const void* p) {
    uint32_t a;
    asm("{ .reg .u64 t; cvta.to.shared.u64 t, %1; cvt.u32.u64 %0, t; }"
        : "=r"(a) : "l"(p));
    return a;
}
__device__ __forceinline__ void ldsm_x4(uint r[4], uint32_t addr) {
    asm volatile("ldmatrix.sync.aligned.m8n8.x4.shared.b16 {%0,%1,%2,%3}, [%4];"
                 : "=r"(r[0]), "=r"(r[1]), "=r"(r[2]), "=r"(r[3]) : "r"(addr));
}
__device__ __forceinline__ void mma_bf16(float c[4], const uint a[4], const uint b0, const uint b1) {
    asm volatile("mma.sync.aligned.m16n8k16.row.col.f32.bf16.bf16.f32 "
                 "{%0,%1,%2,%3},{%4,%5,%6,%7},{%8,%9},{%0,%1,%2,%3};"
                 : "+f"(c[0]), "+f"(c[1]), "+f"(c[2]), "+f"(c[3])
                 : "r"(a[0]), "r"(a[1]), "r"(a[2]), "r"(a[3]), "r"(b0), "r"(b1));
}
__device__ __forceinline__ void cp_async16(uint32_t dst, const void* src) {
    asm volatile("cp.async.cg.shared.global [%0], [%1], 16;" :: "r"(dst), "l"(src));
}
#define CP_COMMIT() asm volatile("cp.async.commit_group;" ::: "memory")
#define CP_WAIT(n)  asm volatile("cp.async.wait_group %0;" :: "n"(n) : "memory")

// ---------------------------------------------------------------------------
__global__ void detect_dtype_kernel(const unsigned int* __restrict__ rows_raw) {
    bool all_hi_zero = true;
    for (int i = 0; i < 64; i++)
        if (rows_raw[2 * i + 1] != 0u) { all_hi_zero = false; break; }
    g_idx64 = all_hi_zero ? 1 : 0;
}

__global__ void zero_cnt_kernel() {
    int i = blockIdx.x * blockDim.x + threadIdx.x;
    if (i < N_NODES) g_cnt[i] = 0;
}

__global__ void __launch_bounds__(512) hist_kernel(const void* __restrict__ rows) {
    const int e = blockIdx.x * blockDim.x + threadIdx.x;
    if (e >= NNZ) return;
    int row = g_idx64 ? (int)((const unsigned int*)rows)[2 * e]
                      : ((const int*)rows)[e];
    atomicAdd(&g_cnt[row], 1);
}

__global__ void __launch_bounds__(1024, 1) scan_kernel() {
    __shared__ int wsum[32];
    __shared__ int carry;
    const int tid = threadIdx.x, lane = tid & 31, wid = tid >> 5;
    if (tid == 0) carry = 0;
    __syncthreads();
    for (int base = 0; base < N_NODES; base += 1024) {
        const int i = base + tid;
        int v = (i < N_NODES) ? g_cnt[i] : 0;
        int x = v;
#pragma unroll
        for (int off = 1; off < 32; off <<= 1) {
            int y = __shfl_up_sync(0xffffffffu, x, off);
            if (lane >= off) x += y;
        }
        if (lane == 31) wsum[wid] = x;
        __syncthreads();
        if (wid == 0) {
            int s = wsum[lane];
#pragma unroll
            for (int off = 1; off < 32; off <<= 1) {
                int y = __shfl_up_sync(0xffffffffu, s, off);
                if (lane >= off) s += y;
            }
            wsum[lane] = s;
        }
        __syncthreads();
        const int warpOff = (wid == 0) ? 0 : wsum[wid - 1];
        const int excl = carry + warpOff + x - v;
        if (i < N_NODES) { g_start[i] = excl; g_cursor[i] = excl; }
        __syncthreads();
        if (tid == 0) carry += wsum[31];
        __syncthreads();
    }
    if (tid == 0) g_start[N_NODES] = carry;
}

__global__ void __launch_bounds__(512)
fill_kernel(const void* __restrict__ rows,
            const void* __restrict__ cols,
            const float* __restrict__ vals) {
    const int e = blockIdx.x * blockDim.x + threadIdx.x;
    if (e >= NNZ) return;
    int row, col;
    if (g_idx64) {
        row = (int)((const unsigned int*)rows)[2 * e];
        col = (int)((const unsigned int*)cols)[2 * e];
    } else {
        row = ((const int*)rows)[e];
        col = ((const int*)cols)[e];
    }
    const int pos = atomicAdd(&g_cursor[row], 1);
    g_edge[pos] = make_int2(col, __float_as_int(vals[e]));
}

// ---------------------------------------------------------------------------
__global__ void prep_x_kernel(const float* __restrict__ X) {
    const int id = blockIdx.x * blockDim.x + threadIdx.x;
    if (id >= (N_PAD * DIN) / 8) return;
    const size_t base = (size_t)id * 8;
    const int row = (int)(base >> 7);
    __nv_bfloat16 h[8], l[8];
    if (row < N_NODES) {
        float v[8];
        *(float4*)&v[0] = *(const float4*)(X + base);
        *(float4*)&v[4] = *(const float4*)(X + base + 4);
#pragma unroll
        for (int i = 0; i < 8; i++) {
            h[i] = __float2bfloat16_rn(v[i]);
            l[i] = __float2bfloat16_rn(v[i] - __bfloat162float(h[i]));
        }
    } else {
#pragma unroll
        for (int i = 0; i < 8; i++) { h[i] = __float2bfloat16_rn(0.f); l[i] = h[i]; }
    }
    *(uint4*)(g_Xh + base) = *(uint4*)h;
    *(uint4*)(g_Xl + base) = *(uint4*)l;
}

__global__ void prep_bt_kernel(const float* __restrict__ basis) {
    const int id = blockIdx.x * blockDim.x + threadIdx.x;
    if (id >= B_BASES * DOUT * (DIN / 4)) return;
    const int k4 = (id & 31) * 4;
    const int n  = (id >> 5) & 127;
    const int b  = id >> 12;
    __nv_bfloat16 h[4], l[4];
#pragma unroll
    for (int i = 0; i < 4; i++) {
        float v = basis[(size_t)b * DIN * DOUT + (size_t)(k4 + i) * DOUT + n];
        h[i] = __float2bfloat16_rn(v);
        l[i] = __float2bfloat16_rn(v - __bfloat162float(h[i]));
    }
    const size_t off = (size_t)b * DOUT * DIN + (size_t)n * DIN + k4;
    *(uint2*)(g_BTh + off) = *(uint2*)h;
    *(uint2*)(g_BTl + off) = *(uint2*)l;
}

// ---------------------------------------------------------------------------
// XB[b] = X @ basis[b] via mma.sync bf16 split-3, cp.async double-buffered.
// grid (391, 8), 256 threads, 2 CTAs/SM (96 KB smem). Epilogue stores fp16.
// Inner loop: Bh+Bl ldsm issued back-to-back so Bh MMAs shadow Bl latency.
// ---------------------------------------------------------------------------
#define S_BH   0
#define S_BL   32768
#define S_X    65536
#define XBUF   16384
#define S_TOTAL 98304

__global__ void __launch_bounds__(256, 2)
gemm_mma_kernel(int dummy) {
    extern __shared__ __align__(1024) unsigned char smem[];
    const uint32_t sbase = smem_u32(smem);
    const int tid  = threadIdx.x;
    const int wid  = tid >> 5;
    const int lane = tid & 31;
    const int b    = blockIdx.y;
    const int m0   = blockIdx.x * 128;

    const int wm = wid >> 1;
    const int wn = wid & 1;

    {
        const size_t bBase = (size_t)b * DOUT * DIN;
#pragma unroll
        for (int i = 0; i < 8; i++) {
            const int slot = i * 256 + tid;
            const int row  = slot >> 4;
            const int c    = slot & 15;
            const uint32_t dst = (uint32_t)(row * 256 + ((c ^ (row & 7)) << 4));
            const size_t src = bBase + (size_t)row * DIN + c * 8;
            cp_async16(sbase + S_BH + dst, g_BTh + src);
            cp_async16(sbase + S_BL + dst, g_BTl + src);
        }
    }
    CP_COMMIT();
#pragma unroll
    for (int i = 0; i < 2; i++) {
        const int slot = i * 256 + tid;
        const int row  = slot >> 2;
        const int c    = slot & 3;
        const uint32_t dst = (uint32_t)(row * 64 + ((c ^ ((row >> 1) & 3)) << 4));
        const size_t src = (size_t)(m0 + row) * DIN + c * 8;
        cp_async16(sbase + S_X + dst, g_Xh + src);
        cp_async16(sbase + S_X + 8192 + dst, g_Xl + src);
    }
    CP_COMMIT();

    float acc[2][8][4];
#pragma unroll
    for (int mf = 0; mf < 2; mf++)
#pragma unroll
        for (int nf = 0; nf < 8; nf++)
#pragma unroll
            for (int q = 0; q < 4; q++) acc[mf][nf][q] = 0.f;

    const int a_row0 = wm * 32 + (lane & 15);
    const int a_ch   = lane >> 4;
    const int b_row0 = wn * 64 + (lane & 7) + ((lane >> 4) << 3);
    const int b_ch   = (lane >> 3) & 1;

#pragma unroll
    for (int kc = 0; kc < 4; kc++) {
        if (kc < 3) {
            const uint32_t xb = sbase + S_X + ((kc + 1) & 1) * XBUF;
#pragma unroll
            for (int i = 0; i < 2; i++) {
                const int slot = i * 256 + tid;
                const int row  = slot >> 2;
                const int c    = slot & 3;
                const uint32_t dst = (uint32_t)(row * 64 + ((c ^ ((row >> 1) & 3)) << 4));
                const size_t src = (size_t)(m0 + row) * DIN + (kc + 1) * 32 + c * 8;
                cp_async16(xb + dst, g_Xh + src);
                cp_async16(xb + 8192 + dst, g_Xl + src);
            }
            CP_COMMIT();
            CP_WAIT(1);
        } else {
            CP_WAIT(0);
        }
        __syncthreads();

        const uint32_t xh = sbase + S_X + (kc & 1) * XBUF;
        const uint32_t xl = xh + 8192;

#pragma unroll
        for (int kfi = 0; kfi < 2; kfi++) {
            const int kf = kc * 2 + kfi;
            uint Ah[2][4], Al[2][4];
#pragma unroll
            for (int mf = 0; mf < 2; mf++) {
                const int row = a_row0 + mf * 16;
                const uint32_t addr = (uint32_t)(row * 64 +
                    (((kfi * 2 + a_ch) ^ ((row >> 1) & 3)) << 4));
                ldsm_x4(Ah[mf], xh + addr);
                ldsm_x4(Al[mf], xl + addr);
            }
#pragma unroll
            for (int p = 0; p < 4; p++) {
                const int row = b_row0 + p * 16;
                const uint32_t addr = (uint32_t)(row * 256 +
                    (((kf * 2 + b_ch) ^ (row & 7)) << 4));
                uint Bh[4], Bl[4];
                ldsm_x4(Bh, sbase + S_BH + addr);
                ldsm_x4(Bl, sbase + S_BL + addr);
                // 8 Bh-dependent MMAs shadow the Bl ldsm latency
#pragma unroll
                for (int mf = 0; mf < 2; mf++) {
                    mma_bf16(acc[mf][2 * p],     Ah[mf], Bh[0], Bh[1]);
                    mma_bf16(acc[mf][2 * p + 1], Ah[mf], Bh[2], Bh[3]);
                    mma_bf16(acc[mf][2 * p],     Al[mf], Bh[0], Bh[1]);
                    mma_bf16(acc[mf][2 * p + 1], Al[mf], Bh[2], Bh[3]);
                }
#pragma unroll
                for (int mf = 0; mf < 2; mf++) {
                    mma_bf16(acc[mf][2 * p],     Ah[mf], Bl[0], Bl[1]);
                    mma_bf16(acc[mf][2 * p + 1], Ah[mf], Bl[2], Bl[3]);
                }
            }
        }
        __syncthreads();
    }

    // --- epilogue: write XB[b] fp16 ---
    __half* outBase = g_XB + (size_t)b * N_NODES * DOUT;
    const int g = lane >> 2;
    const int t2 = (lane & 3) * 2;
#pragma unroll
    for (int mf = 0; mf < 2; mf++) {
        const int r0 = m0 + wm * 32 + mf * 16 + g;
#pragma unroll
        for (int nf = 0; nf < 8; nf++) {
            const int col = wn * 64 + nf * 8 + t2;
            if (r0 < N_NODES) {
                __half2 h = __floats2half2_rn(acc[mf][nf][0], acc[mf][nf][1]);
                *(uint32_t*)(outBase + (size_t)r0 * DOUT + col) = *(uint32_t*)&h;
            }
            if (r0 + 8 < N_NODES) {
                __half2 h = __floats2half2_rn(acc[mf][nf][2], acc[mf][nf][3]);
                *(uint32_t*)(outBase + (size_t)(r0 + 8) * DOUT + col) = *(uint32_t*)&h;
            }
        }
    }
}

// ---------------------------------------------------------------------------
// FW[r][n][d] = sum_b comp[r][b] * XB[b][n][d]   (fp16 in, fp32 math, fp16 out)
// ---------------------------------------------------------------------------
__global__ __launch_bounds__(256)
void combine_kernel(const float* __restrict__ comp) {
    __shared__ float cs[R_REL * B_BASES];
    if (threadIdx.x < R_REL * B_BASES) cs[threadIdx.x] = comp[threadIdx.x];
    __syncthreads();

    const int id = blockIdx.x * blockDim.x + threadIdx.x;
    if (id >= N_NODES * 32) return;
    const int n  = id >> 5;
    const int d4 = (id & 31) * 4;

    float4 xb[8];
#pragma unroll
    for (int b = 0; b < B_BASES; b++) {
        const uint2 pk = __ldg((const uint2*)(g_XB + ((size_t)b * N_NODES + n) * DOUT + d4));
        const float2 a = __half22float2(*(const __half2*)&pk.x);
        const float2 c = __half22float2(*(const __half2*)&pk.y);
        xb[b] = make_float4(a.x, a.y, c.x, c.y);
    }

#pragma unroll
    for (int r = 0; r < R_REL; r++) {
        float4 o = make_float4(0.f, 0.f, 0.f, 0.f);
#pragma unroll
        for (int b = 0; b < B_BASES; b++) {
            const float c = cs[r * B_BASES + b];
            o.x += c * xb[b].x;
            o.y += c * xb[b].y;
            o.z += c * xb[b].z;
            o.w += c * xb[b].w;
        }
        __half2 h0 = __floats2half2_rn(o.x, o.y);
        __half2 h1 = __floats2half2_rn(o.z, o.w);
        uint2 pk;
        pk.x = *(uint32_t*)&h0;
        pk.y = *(uint32_t*)&h1;
        *(uint2*)(g_FW + ((size_t)r * N_NODES + n) * DOUT + d4) = pk;
    }
}

// ---------------------------------------------------------------------------
// Sorted scatter: one warp per output row; fp16 FW gather (8 B/lane/edge),
// unroll-8 for MLP, fp32 accumulation, single non-atomic fp32 row write.
// ---------------------------------------------------------------------------
__device__ __forceinline__ float4 fw_row_f4(int col, int lane) {
    const uint2 pk = __ldg((const uint2*)(g_FW + (size_t)col * DOUT) + lane);
    const float2 a = __half22float2(*(const __half2*)&pk.x);
    const float2 b = __half22float2(*(const __half2*)&pk.y);
    return make_float4(a.x, a.y, b.x, b.y);
}

__global__ void __launch_bounds__(256)
scatter2_kernel(float* __restrict__ out) {
    const int warpId = (blockIdx.x * blockDim.x + threadIdx.x) >> 5;
    if (warpId >= N_NODES) return;
    const int lane = threadIdx.x & 31;

    const int s = g_start[warpId];
    const int e = g_start[warpId + 1];

    float4 acc0 = make_float4(0.f, 0.f, 0.f, 0.f);
    float4 acc1 = make_float4(0.f, 0.f, 0.f, 0.f);
    int i = s;
    for (; i + 8 <= e; i += 8) {
        int2 ed[8];
#pragma unroll
        for (int q = 0; q < 8; q++) ed[q] = __ldg(&g_edge[i + q]);
        float4 f[8];
#pragma unroll
        for (int q = 0; q < 8; q++) f[q] = fw_row_f4(ed[q].x, lane);
#pragma unroll
        for (int q = 0; q < 8; q += 2) {
            const float v0 = __int_as_float(ed[q].y);
            const float v1 = __int_as_float(ed[q + 1].y);
            acc0.x += v0 * f[q].x;     acc1.x += v1 * f[q + 1].x;
            acc0.y += v0 * f[q].y;     acc1.y += v1 * f[q + 1].y;
            acc0.z += v0 * f[q].z;     acc1.z += v1 * f[q + 1].z;
            acc0.w += v0 * f[q].w;     acc1.w += v1 * f[q + 1].w;
        }
    }
    for (; i < e; i++) {
        int2 ed = __ldg(&g_edge[i]);
        float4 f = fw_row_f4(ed.x, lane);
        const float v = __int_as_float(ed.y);
        acc0.x += v * f.x; acc0.y += v * f.y; acc0.z += v * f.z; acc0.w += v * f.w;
    }
    acc0.x += acc1.x; acc0.y += acc1.y; acc0.z += acc1.z; acc0.w += acc1.w;
    *(float4*)(out + (size_t)warpId * DOUT + lane * 4) = acc0;
}

// ---------------------------------------------------------------------------
extern "C" void kernel_launch(void* const* d_in, const int* in_sizes, int n_in,
                              void* d_out, int out_size) {
    const float* X      = (const float*)d_in[0];
    const void*  A_rows = d_in[1];
    const void*  A_cols = d_in[2];
    const float* A_vals = (const float*)d_in[3];
    const float* basis  = (const float*)d_in[4];
    const float* comp   = (const float*)d_in[5];
    float* out = (float*)d_out;

    cudaFuncSetAttribute(gemm_mma_kernel,
                         cudaFuncAttributeMaxDynamicSharedMemorySize, S_TOTAL);

    // gemm_mma_kernel stays launch #4 so ncu (-s 5 -c 1) profiles it.
    detect_dtype_kernel<<<1, 1>>>((const unsigned int*)A_rows);         // 1

    const int px = (N_PAD * DIN) / 8;
    prep_x_kernel<<<(px + 255) / 256, 256>>>(X);                        // 2
    const int pb = B_BASES * DOUT * (DIN / 4);
    prep_bt_kernel<<<(pb + 255) / 256, 256>>>(basis);                   // 3

    dim3 ggrid(M_TILES, B_BASES);
    gemm_mma_kernel<<<ggrid, 256, S_TOTAL>>>(0);                        // 4 (profiled)

    zero_cnt_kernel<<<(N_NODES + 511) / 512, 512>>>();                  // 5
    hist_kernel<<<(NNZ + 511) / 512, 512>>>(A_rows);                    // 6
    scan_kernel<<<1, 1024>>>();                                         // 7
    fill_kernel<<<(NNZ + 511) / 512, 512>>>(A_rows, A_cols, A_vals);    // 8

    const int cthreads = N_NODES * 32;
    combine_kernel<<<(cthreads + 255) / 256, 256>>>(comp);              // 9

    const long long sthreads = (long long)N_NODES * 32;
    scatter2_kernel<<<(unsigned)((sthreads + 255) / 256), 256>>>(out);  // 10
}

// round 12
// speedup vs baseline: 1.2527x; 1.2527x over previous
#include <cuda_runtime.h>
#include <cuda_bf16.h>
#include <cuda_fp16.h>
#include <cstdint>

#define N_NODES 50000
#define N_PAD   50048          // 391 * 128
#define R_REL   16
#define B_BASES 8
#define DIN     128
#define DOUT    128
#define NNZ     1600000
#define M_TILES 391

typedef unsigned int uint;

// Scratch: device globals (no allocation allowed)
__device__ __nv_bfloat16 g_Xh[(size_t)N_PAD * DIN];
__device__ __nv_bfloat16 g_Xl[(size_t)N_PAD * DIN];
__device__ __nv_bfloat16 g_BTh[B_BASES * DOUT * DIN];
__device__ __nv_bfloat16 g_BTl[B_BASES * DOUT * DIN];
__device__ __half g_XB[(size_t)B_BASES * N_NODES * DOUT];   // 102.4 MB (fp16)
__device__ __half g_FW[(size_t)R_REL * N_NODES * DOUT];     // 204.8 MB (fp16)
__device__ int    g_idx64;
// CSR binning scratch
__device__ int   g_cnt[N_NODES];
__device__ int   g_start[N_NODES + 1];
__device__ int   g_cursor[N_NODES];
__device__ int2  g_edge[NNZ];

// ---------------------------------------------------------------------------
__device__ __forceinline__ uint32_t smem_u32(const void* p) {
    uint32_t a;
    asm("{ .reg .u64 t; cvta.to.shared.u64 t, %1; cvt.u32.u64 %0, t; }"
        : "=r"(a) : "l"(p));
    return a;
}
__device__ __forceinline__ void ldsm_x4(uint r[4], uint32_t addr) {
    asm volatile("ldmatrix.sync.aligned.m8n8.x4.shared.b16 {%0,%1,%2,%3}, [%4];"
                 : "=r"(r[0]), "=r"(r[1]), "=r"(r[2]), "=r"(r[3]) : "r"(addr));
}
__device__ __forceinline__ void mma_bf16(float c[4], const uint a[4], const uint b0, const uint b1) {
    asm volatile("mma.sync.aligned.m16n8k16.row.col.f32.bf16.bf16.f32 "
                 "{%0,%1,%2,%3},{%4,%5,%6,%7},{%8,%9},{%0,%1,%2,%3};"
                 : "+f"(c[0]), "+f"(c[1]), "+f"(c[2]), "+f"(c[3])
                 : "r"(a[0]), "r"(a[1]), "r"(a[2]), "r"(a[3]), "r"(b0), "r"(b1));
}
__device__ __forceinline__ void cp_async16(uint32_t dst, const void* src) {
    asm volatile("cp.async.cg.shared.global [%0], [%1], 16;" :: "r"(dst), "l"(src));
}
#define CP_COMMIT() asm volatile("cp.async.commit_group;" ::: "memory")
#define CP_WAIT(n)  asm volatile("cp.async.wait_group %0;" :: "n"(n) : "memory")

// ---------------------------------------------------------------------------
__global__ void detect_dtype_kernel(const unsigned int* __restrict__ rows_raw) {
    bool all_hi_zero = true;
    for (int i = 0; i < 64; i++)
        if (rows_raw[2 * i + 1] != 0u) { all_hi_zero = false; break; }
    g_idx64 = all_hi_zero ? 1 : 0;
}

__global__ void zero_cnt_kernel() {
    int i = blockIdx.x * blockDim.x + threadIdx.x;
    if (i < N_NODES) g_cnt[i] = 0;
}

__global__ void hist_kernel(const void* __restrict__ rows) {
    const int e = blockIdx.x * blockDim.x + threadIdx.x;
    if (e >= NNZ) return;
    int row = g_idx64 ? (int)((const unsigned int*)rows)[2 * e]
                      : ((const int*)rows)[e];
    atomicAdd(&g_cnt[row], 1);
}

__global__ void __launch_bounds__(1024, 1) scan_kernel() {
    __shared__ int wsum[32];
    __shared__ int carry;
    const int tid = threadIdx.x, lane = tid & 31, wid = tid >> 5;
    if (tid == 0) carry = 0;
    __syncthreads();
    for (int base = 0; base < N_NODES; base += 1024) {
        const int i = base + tid;
        int v = (i < N_NODES) ? g_cnt[i] : 0;
        int x = v;
#pragma unroll
        for (int off = 1; off < 32; off <<= 1) {
            int y = __shfl_up_sync(0xffffffffu, x, off);
            if (lane >= off) x += y;
        }
        if (lane == 31) wsum[wid] = x;
        __syncthreads();
        if (wid == 0) {
            int s = wsum[lane];
#pragma unroll
            for (int off = 1; off < 32; off <<= 1) {
                int y = __shfl_up_sync(0xffffffffu, s, off);
                if (lane >= off) s += y;
            }
            wsum[lane] = s;
        }
        __syncthreads();
        const int warpOff = (wid == 0) ? 0 : wsum[wid - 1];
        const int excl = carry + warpOff + x - v;
        if (i < N_NODES) { g_start[i] = excl; g_cursor[i] = excl; }
        __syncthreads();
        if (tid == 0) carry += wsum[31];
        __syncthreads();
    }
    if (tid == 0) g_start[N_NODES] = carry;
}

__global__ void fill_kernel(const void* __restrict__ rows,
                            const void* __restrict__ cols,
                            const float* __restrict__ vals) {
    const int e = blockIdx.x * blockDim.x + threadIdx.x;
    if (e >= NNZ) return;
    int row, col;
    if (g_idx64) {
        row = (int)((const unsigned int*)rows)[2 * e];
        col = (int)((const unsigned int*)cols)[2 * e];
    } else {
        row = ((const int*)rows)[e];
        col = ((const int*)cols)[e];
    }
    const int pos = atomicAdd(&g_cursor[row], 1);
    g_edge[pos] = make_int2(col, __float_as_int(vals[e]));
}

// ---------------------------------------------------------------------------
__global__ void prep_x_kernel(const float* __restrict__ X) {
    const int id = blockIdx.x * blockDim.x + threadIdx.x;
    if (id >= (N_PAD * DIN) / 8) return;
    const size_t base = (size_t)id * 8;
    const int row = (int)(base >> 7);
    __nv_bfloat16 h[8], l[8];
    if (row < N_NODES) {
        float v[8];
        *(float4*)&v[0] = *(const float4*)(X + base);
        *(float4*)&v[4] = *(const float4*)(X + base + 4);
#pragma unroll
        for (int i = 0; i < 8; i++) {
            h[i] = __float2bfloat16_rn(v[i]);
            l[i] = __float2bfloat16_rn(v[i] - __bfloat162float(h[i]));
        }
    } else {
#pragma unroll
        for (int i = 0; i < 8; i++) { h[i] = __float2bfloat16_rn(0.f); l[i] = h[i]; }
    }
    *(uint4*)(g_Xh + base) = *(uint4*)h;
    *(uint4*)(g_Xl + base) = *(uint4*)l;
}

__global__ void prep_bt_kernel(const float* __restrict__ basis) {
    const int id = blockIdx.x * blockDim.x + threadIdx.x;
    if (id >= B_BASES * DOUT * (DIN / 4)) return;
    const int k4 = (id & 31) * 4;
    const int n  = (id >> 5) & 127;
    const int b  = id >> 12;
    __nv_bfloat16 h[4], l[4];
#pragma unroll
    for (int i = 0; i < 4; i++) {
        float v = basis[(size_t)b * DIN * DOUT + (size_t)(k4 + i) * DOUT + n];
        h[i] = __float2bfloat16_rn(v);
        l[i] = __float2bfloat16_rn(v - __bfloat162float(h[i]));
    }
    const size_t off = (size_t)b * DOUT * DIN + (size_t)n * DIN + k4;
    *(uint2*)(g_BTh + off) = *(uint2*)h;
    *(uint2*)(g_BTl + off) = *(uint2*)l;
}

// ---------------------------------------------------------------------------
// XB[b] = X @ basis[b] via mma.sync bf16 split-3, cp.async double-buffered.
// grid (391, 8), 256 threads, 2 CTAs/SM (96 KB smem). Epilogue stores fp16.
// (Exact R10 version — known-good 101 us.)
// ---------------------------------------------------------------------------
#define S_BH   0
#define S_BL   32768
#define S_X    65536
#define XBUF   16384
#define S_TOTAL 98304

__global__ void __launch_bounds__(256, 2)
gemm_mma_kernel(int dummy) {
    extern __shared__ __align__(1024) unsigned char smem[];
    const uint32_t sbase = smem_u32(smem);
    const int tid  = threadIdx.x;
    const int wid  = tid >> 5;
    const int lane = tid & 31;
    const int b    = blockIdx.y;
    const int m0   = blockIdx.x * 128;

    const int wm = wid >> 1;
    const int wn = wid & 1;

    {
        const size_t bBase = (size_t)b * DOUT * DIN;
#pragma unroll
        for (int i = 0; i < 8; i++) {
            const int slot = i * 256 + tid;
            const int row  = slot >> 4;
            const int c    = slot & 15;
            const uint32_t dst = (uint32_t)(row * 256 + ((c ^ (row & 7)) << 4));
            const size_t src = bBase + (size_t)row * DIN + c * 8;
            cp_async16(sbase + S_BH + dst, g_BTh + src);
            cp_async16(sbase + S_BL + dst, g_BTl + src);
        }
    }
    CP_COMMIT();
#pragma unroll
    for (int i = 0; i < 2; i++) {
        const int slot = i * 256 + tid;
        const int row  = slot >> 2;
        const int c    = slot & 3;
        const uint32_t dst = (uint32_t)(row * 64 + ((c ^ ((row >> 1) & 3)) << 4));
        const size_t src = (size_t)(m0 + row) * DIN + c * 8;
        cp_async16(sbase + S_X + dst, g_Xh + src);
        cp_async16(sbase + S_X + 8192 + dst, g_Xl + src);
    }
    CP_COMMIT();

    float acc[2][8][4];
#pragma unroll
    for (int mf = 0; mf < 2; mf++)
#pragma unroll
        for (int nf = 0; nf < 8; nf++)
#pragma unroll
            for (int q = 0; q < 4; q++) acc[mf][nf][q] = 0.f;

    const int a_row0 = wm * 32 + (lane & 15);
    const int a_ch   = lane >> 4;
    const int b_row0 = wn * 64 + (lane & 7) + ((lane >> 4) << 3);
    const int b_ch   = (lane >> 3) & 1;

#pragma unroll
    for (int kc = 0; kc < 4; kc++) {
        if (kc < 3) {
            const uint32_t xb = sbase + S_X + ((kc + 1) & 1) * XBUF;
#pragma unroll
            for (int i = 0; i < 2; i++) {
                const int slot = i * 256 + tid;
                const int row  = slot >> 2;
                const int c    = slot & 3;
                const uint32_t dst = (uint32_t)(row * 64 + ((c ^ ((row >> 1) & 3)) << 4));
                const size_t src = (size_t)(m0 + row) * DIN + (kc + 1) * 32 + c * 8;
                cp_async16(xb + dst, g_Xh + src);
                cp_async16(xb + 8192 + dst, g_Xl + src);
            }
            CP_COMMIT();
            CP_WAIT(1);
        } else {
            CP_WAIT(0);
        }
        __syncthreads();

        const uint32_t xh = sbase + S_X + (kc & 1) * XBUF;
        const uint32_t xl = xh + 8192;

#pragma unroll
        for (int kfi = 0; kfi < 2; kfi++) {
            const int kf = kc * 2 + kfi;
            uint Ah[2][4], Al[2][4];
#pragma unroll
            for (int mf = 0; mf < 2; mf++) {
                const int row = a_row0 + mf * 16;
                const uint32_t addr = (uint32_t)(row * 64 +
                    (((kfi * 2 + a_ch) ^ ((row >> 1) & 3)) << 4));
                ldsm_x4(Ah[mf], xh + addr);
                ldsm_x4(Al[mf], xl + addr);
            }
#pragma unroll
            for (int p = 0; p < 4; p++) {
                const int row = b_row0 + p * 16;
                const uint32_t addr = (uint32_t)(row * 256 +
                    (((kf * 2 + b_ch) ^ (row & 7)) << 4));
                uint Bh[4];
                ldsm_x4(Bh, sbase + S_BH + addr);
#pragma unroll
                for (int mf = 0; mf < 2; mf++) {
                    mma_bf16(acc[mf][2 * p],     Ah[mf], Bh[0], Bh[1]);
                    mma_bf16(acc[mf][2 * p + 1], Ah[mf], Bh[2], Bh[3]);
                    mma_bf16(acc[mf][2 * p],     Al[mf], Bh[0], Bh[1]);
                    mma_bf16(acc[mf][2 * p + 1], Al[mf], Bh[2], Bh[3]);
                }
                uint Bl[4];
                ldsm_x4(Bl, sbase + S_BL + addr);
#pragma unroll
                for (int mf = 0; mf < 2; mf++) {
                    mma_bf16(acc[mf][2 * p],     Ah[mf], Bl[0], Bl[1]);
                    mma_bf16(acc[mf][2 * p + 1], Ah[mf], Bl[2], Bl[3]);
                }
            }
        }
        __syncthreads();
    }

    // --- epilogue: write XB[b] fp16 ---
    __half* outBase = g_XB + (size_t)b * N_NODES * DOUT;
    const int g = lane >> 2;
    const int t2 = (lane & 3) * 2;
#pragma unroll
    for (int mf = 0; mf < 2; mf++) {
        const int r0 = m0 + wm * 32 + mf * 16 + g;
#pragma unroll
        for (int nf = 0; nf < 8; nf++) {
            const int col = wn * 64 + nf * 8 + t2;
            if (r0 < N_NODES) {
                __half2 h = __floats2half2_rn(acc[mf][nf][0], acc[mf][nf][1]);
                *(uint32_t*)(outBase + (size_t)r0 * DOUT + col) = *(uint32_t*)&h;
            }
            if (r0 + 8 < N_NODES) {
                __half2 h = __floats2half2_rn(acc[mf][nf][2], acc[mf][nf][3]);
                *(uint32_t*)(outBase + (size_t)(r0 + 8) * DOUT + col) = *(uint32_t*)&h;
            }
        }
    }
}

// ---------------------------------------------------------------------------
// FW[r][n][d] = sum_b comp[r][b] * XB[b][n][d]   (fp16 in, fp32 math, fp16 out)
// ---------------------------------------------------------------------------
__global__ __launch_bounds__(256)
void combine_kernel(const float* __restrict__ comp) {
    __shared__ float cs[R_REL * B_BASES];
    if (threadIdx.x < R_REL * B_BASES) cs[threadIdx.x] = comp[threadIdx.x];
    __syncthreads();

    const int id = blockIdx.x * blockDim.x + threadIdx.x;
    if (id >= N_NODES * 32) return;
    const int n  = id >> 5;
    const int d4 = (id & 31) * 4;

    float4 xb[8];
#pragma unroll
    for (int b = 0; b < B_BASES; b++) {
        const uint2 pk = __ldg((const uint2*)(g_XB + ((size_t)b * N_NODES + n) * DOUT + d4));
        const float2 a = __half22float2(*(const __half2*)&pk.x);
        const float2 c = __half22float2(*(const __half2*)&pk.y);
        xb[b] = make_float4(a.x, a.y, c.x, c.y);
    }

#pragma unroll
    for (int r = 0; r < R_REL; r++) {
        float4 o = make_float4(0.f, 0.f, 0.f, 0.f);
#pragma unroll
        for (int b = 0; b < B_BASES; b++) {
            const float c = cs[r * B_BASES + b];
            o.x += c * xb[b].x;
            o.y += c * xb[b].y;
            o.z += c * xb[b].z;
            o.w += c * xb[b].w;
        }
        __half2 h0 = __floats2half2_rn(o.x, o.y);
        __half2 h1 = __floats2half2_rn(o.z, o.w);
        uint2 pk;
        pk.x = *(uint32_t*)&h0;
        pk.y = *(uint32_t*)&h1;
        *(uint2*)(g_FW + ((size_t)r * N_NODES + n) * DOUT + d4) = pk;
    }
}

// ---------------------------------------------------------------------------
// Sorted scatter: one warp per output row; fp16 FW gather (8 B/lane/edge),
// unroll-4 (R10 shape), fp32 accumulation, single non-atomic row write.
// ---------------------------------------------------------------------------
__device__ __forceinline__ float4 fw_row_f4(int col, int lane) {
    const uint2 pk = __ldg((const uint2*)(g_FW + (size_t)col * DOUT) + lane);
    const float2 a = __half22float2(*(const __half2*)&pk.x);
    const float2 b = __half22float2(*(const __half2*)&pk.y);
    return make_float4(a.x, a.y, b.x, b.y);
}

__global__ void __launch_bounds__(256)
scatter2_kernel(float* __restrict__ out) {
    const int warpId = (blockIdx.x * blockDim.x + threadIdx.x) >> 5;
    if (warpId >= N_NODES) return;
    const int lane = threadIdx.x & 31;

    const int s = g_start[warpId];
    const int e = g_start[warpId + 1];

    float4 acc = make_float4(0.f, 0.f, 0.f, 0.f);
    int i = s;
    for (; i + 4 <= e; i += 4) {
        int2 e0 = g_edge[i], e1 = g_edge[i + 1], e2 = g_edge[i + 2], e3 = g_edge[i + 3];
        float4 f0 = fw_row_f4(e0.x, lane);
        float4 f1 = fw_row_f4(e1.x, lane);
        float4 f2 = fw_row_f4(e2.x, lane);
        float4 f3 = fw_row_f4(e3.x, lane);
        const float v0 = __int_as_float(e0.y), v1 = __int_as_float(e1.y);
        const float v2 = __int_as_float(e2.y), v3 = __int_as_float(e3.y);
        acc.x += v0 * f0.x + v1 * f1.x + v2 * f2.x + v3 * f3.x;
        acc.y += v0 * f0.y + v1 * f1.y + v2 * f2.y + v3 * f3.y;
        acc.z += v0 * f0.z + v1 * f1.z + v2 * f2.z + v3 * f3.z;
        acc.w += v0 * f0.w + v1 * f1.w + v2 * f2.w + v3 * f3.w;
    }
    for (; i < e; i++) {
        int2 ed = g_edge[i];
        float4 f = fw_row_f4(ed.x, lane);
        const float v = __int_as_float(ed.y);
        acc.x += v * f.x; acc.y += v * f.y; acc.z += v * f.z; acc.w += v * f.w;
    }
    *(float4*)(out + (size_t)warpId * DOUT + lane * 4) = acc;
}

// ---------------------------------------------------------------------------
// Two capture streams: sort pipeline (zero/hist/scan/fill) forks after
// detect_dtype and runs concurrently with the GEMM chain; joins before
// scatter2. Stream/event creation is not a captured op and not a device
// allocation; created per call (deterministic), intentionally not destroyed
// (kernel_launch is only invoked for correctness + capture, not per replay).
// ---------------------------------------------------------------------------
extern "C" void kernel_launch(void* const* d_in, const int* in_sizes, int n_in,
                              void* d_out, int out_size) {
    const float* X      = (const float*)d_in[0];
    const void*  A_rows = d_in[1];
    const void*  A_cols = d_in[2];
    const float* A_vals = (const float*)d_in[3];
    const float* basis  = (const float*)d_in[4];
    const float* comp   = (const float*)d_in[5];
    float* out = (float*)d_out;

    cudaFuncSetAttribute(gemm_mma_kernel,
                         cudaFuncAttributeMaxDynamicSharedMemorySize, S_TOTAL);

    cudaStream_t s2;
    cudaStreamCreateWithFlags(&s2, cudaStreamNonBlocking);
    cudaEvent_t evFork, evJoin;
    cudaEventCreateWithFlags(&evFork, cudaEventDisableTiming);
    cudaEventCreateWithFlags(&evJoin, cudaEventDisableTiming);

    // main stream: dtype detection (needed by both chains)
    detect_dtype_kernel<<<1, 1>>>((const unsigned int*)A_rows);

    // fork side stream
    cudaEventRecord(evFork, 0);
    cudaStreamWaitEvent(s2, evFork, 0);

    // side stream: CSR sort pipeline
    zero_cnt_kernel<<<(N_NODES + 255) / 256, 256, 0, s2>>>();
    hist_kernel<<<(NNZ + 255) / 256, 256, 0, s2>>>(A_rows);
    scan_kernel<<<1, 1024, 0, s2>>>();
    fill_kernel<<<(NNZ + 255) / 256, 256, 0, s2>>>(A_rows, A_cols, A_vals);
    cudaEventRecord(evJoin, s2);

    // main stream: GEMM chain
    const int px = (N_PAD * DIN) / 8;
    prep_x_kernel<<<(px + 255) / 256, 256>>>(X);
    const int pb = B_BASES * DOUT * (DIN / 4);
    prep_bt_kernel<<<(pb + 255) / 256, 256>>>(basis);

    dim3 ggrid(M_TILES, B_BASES);
    gemm_mma_kernel<<<ggrid, 256, S_TOTAL>>>(0);

    const int cthreads = N_NODES * 32;
    combine_kernel<<<(cthreads + 255) / 256, 256>>>(comp);

    // join, then final scatter
    cudaStreamWaitEvent(0, evJoin, 0);
    const long long sthreads = (long long)N_NODES * 32;
    scatter2_kernel<<<(unsigned)((sthreads + 255) / 256), 256>>>(out);
}

// round 13
// speedup vs baseline: 1.5003x; 1.1977x over previous
#include <cuda_runtime.h>
#include <cuda_bf16.h>
#include <cuda_fp16.h>
#include <cstdint>

#define N_NODES 50000
#define N_PAD   50048          // 391 * 128
#define R_REL   16
#define B_BASES 8
#define DIN     128
#define DOUT    128
#define NNZ     1600000
#define M_TILES 391

typedef unsigned int uint;

// Scratch: device globals (no allocation allowed)
__device__ __half g_X16[(size_t)N_PAD * DIN];               // 12.8 MB (fp16 X)
__device__ __half g_BT16[B_BASES * DOUT * DIN];             // 256 KB (BT[b][n][k])
__device__ __half g_XB[(size_t)B_BASES * N_NODES * DOUT];   // 102.4 MB (fp16)
__device__ __half g_FW[(size_t)R_REL * N_NODES * DOUT];     // 204.8 MB (fp16)
__device__ int    g_idx64;
// CSR binning scratch
__device__ int   g_cnt[N_NODES];
__device__ int   g_start[N_NODES + 1];
__device__ int   g_cursor[N_NODES];
__device__ int2  g_edge[NNZ];

// ---------------------------------------------------------------------------
__device__ __forceinline__ uint32_t smem_u32(const void* p) {
    uint32_t a;
    asm("{ .reg .u64 t; cvta.to.shared.u64 t, %1; cvt.u32.u64 %0, t; }"
        : "=r"(a) : "l"(p));
    return a;
}
__device__ __forceinline__ void ldsm_x4(uint r[4], uint32_t addr) {
    asm volatile("ldmatrix.sync.aligned.m8n8.x4.shared.b16 {%0,%1,%2,%3}, [%4];"
                 : "=r"(r[0]), "=r"(r[1]), "=r"(r[2]), "=r"(r[3]) : "r"(addr));
}
__device__ __forceinline__ void mma_f16(float c[4], const uint a[4], const uint b0, const uint b1) {
    asm volatile("mma.sync.aligned.m16n8k16.row.col.f32.f16.f16.f32 "
                 "{%0,%1,%2,%3},{%4,%5,%6,%7},{%8,%9},{%0,%1,%2,%3};"
                 : "+f"(c[0]), "+f"(c[1]), "+f"(c[2]), "+f"(c[3])
                 : "r"(a[0]), "r"(a[1]), "r"(a[2]), "r"(a[3]), "r"(b0), "r"(b1));
}
__device__ __forceinline__ void cp_async16(uint32_t dst, const void* src) {
    asm volatile("cp.async.cg.shared.global [%0], [%1], 16;" :: "r"(dst), "l"(src));
}
#define CP_COMMIT() asm volatile("cp.async.commit_group;" ::: "memory")
#define CP_WAIT(n)  asm volatile("cp.async.wait_group %0;" :: "n"(n) : "memory")

// ---------------------------------------------------------------------------
__global__ void detect_dtype_kernel(const unsigned int* __restrict__ rows_raw) {
    bool all_hi_zero = true;
    for (int i = 0; i < 64; i++)
        if (rows_raw[2 * i + 1] != 0u) { all_hi_zero = false; break; }
    g_idx64 = all_hi_zero ? 1 : 0;
}

__global__ void zero_cnt_kernel() {
    int i = blockIdx.x * blockDim.x + threadIdx.x;
    if (i < N_NODES) g_cnt[i] = 0;
}

__global__ void hist_kernel(const void* __restrict__ rows) {
    const int e = blockIdx.x * blockDim.x + threadIdx.x;
    if (e >= NNZ) return;
    int row = g_idx64 ? (int)((const unsigned int*)rows)[2 * e]
                      : ((const int*)rows)[e];
    atomicAdd(&g_cnt[row], 1);
}

__global__ void __launch_bounds__(1024, 1) scan_kernel() {
    __shared__ int wsum[32];
    __shared__ int carry;
    const int tid = threadIdx.x, lane = tid & 31, wid = tid >> 5;
    if (tid == 0) carry = 0;
    __syncthreads();
    for (int base = 0; base < N_NODES; base += 1024) {
        const int i = base + tid;
        int v = (i < N_NODES) ? g_cnt[i] : 0;
        int x = v;
#pragma unroll
        for (int off = 1; off < 32; off <<= 1) {
            int y = __shfl_up_sync(0xffffffffu, x, off);
            if (lane >= off) x += y;
        }
        if (lane == 31) wsum[wid] = x;
        __syncthreads();
        if (wid == 0) {
            int s = wsum[lane];
#pragma unroll
            for (int off = 1; off < 32; off <<= 1) {
                int y = __shfl_up_sync(0xffffffffu, s, off);
                if (lane >= off) s += y;
            }
            wsum[lane] = s;
        }
        __syncthreads();
        const int warpOff = (wid == 0) ? 0 : wsum[wid - 1];
        const int excl = carry + warpOff + x - v;
        if (i < N_NODES) { g_start[i] = excl; g_cursor[i] = excl; }
        __syncthreads();
        if (tid == 0) carry += wsum[31];
        __syncthreads();
    }
    if (tid == 0) g_start[N_NODES] = carry;
}

__global__ void fill_kernel(const void* __restrict__ rows,
                            const void* __restrict__ cols,
                            const float* __restrict__ vals) {
    const int e = blockIdx.x * blockDim.x + threadIdx.x;
    if (e >= NNZ) return;
    int row, col;
    if (g_idx64) {
        row = (int)((const unsigned int*)rows)[2 * e];
        col = (int)((const unsigned int*)cols)[2 * e];
    } else {
        row = ((const int*)rows)[e];
        col = ((const int*)cols)[e];
    }
    const int pos = atomicAdd(&g_cursor[row], 1);
    g_edge[pos] = make_int2(col, __float_as_int(vals[e]));
}

// ---------------------------------------------------------------------------
// X -> fp16 (each thread: 8 floats -> 8 halves = one uint4 store)
__global__ void prep_x_kernel(const float* __restrict__ X) {
    const int id = blockIdx.x * blockDim.x + threadIdx.x;
    if (id >= (N_PAD * DIN) / 8) return;
    const size_t base = (size_t)id * 8;
    const int row = (int)(base >> 7);
    __half h[8];
    if (row < N_NODES) {
        float v[8];
        *(float4*)&v[0] = *(const float4*)(X + base);
        *(float4*)&v[4] = *(const float4*)(X + base + 4);
#pragma unroll
        for (int i = 0; i < 8; i++) h[i] = __float2half_rn(v[i]);
    } else {
#pragma unroll
        for (int i = 0; i < 8; i++) h[i] = __float2half_rn(0.f);
    }
    *(uint4*)(g_X16 + base) = *(uint4*)h;
}

// Transpose basis -> BT[b][n][k] fp16
__global__ void prep_bt_kernel(const float* __restrict__ basis) {
    const int id = blockIdx.x * blockDim.x + threadIdx.x;
    if (id >= B_BASES * DOUT * (DIN / 4)) return;
    const int k4 = (id & 31) * 4;
    const int n  = (id >> 5) & 127;
    const int b  = id >> 12;
    __half h[4];
#pragma unroll
    for (int i = 0; i < 4; i++)
        h[i] = __float2half_rn(basis[(size_t)b * DIN * DOUT + (size_t)(k4 + i) * DOUT + n]);
    const size_t off = (size_t)b * DOUT * DIN + (size_t)n * DIN + k4;
    *(uint2*)(g_BT16 + off) = *(uint2*)h;
}

// ---------------------------------------------------------------------------
// XB[b] = X @ basis[b] via single-product fp16 mma.sync (fp32 accum).
// grid (391, 8), 256 threads, 2 CTAs/SM (48 KB smem), cp.async double buffer.
// B resident full-K (32 KB, 256B rows, swizzle c^(row&7));
// X in 4 k-chunks of 32 (2 x 8 KB, 64B rows, swizzle c^((row>>1)&3)).
// ---------------------------------------------------------------------------
#define S_B    0
#define S_X    32768
#define XBUF   8192
#define S_TOTAL 49152

__global__ void __launch_bounds__(256, 2)
gemm_mma_kernel(int dummy) {
    extern __shared__ __align__(1024) unsigned char smem[];
    const uint32_t sbase = smem_u32(smem);
    const int tid  = threadIdx.x;
    const int wid  = tid >> 5;
    const int lane = tid & 31;
    const int b    = blockIdx.y;
    const int m0   = blockIdx.x * 128;

    const int wm = wid >> 1;          // 0..3 (32 rows)
    const int wn = wid & 1;           // 0..1 (64 cols)

    // --- prologue: async-load B (full K, 2048 chunks, 8/thread), X chunk 0 ---
    {
        const size_t bBase = (size_t)b * DOUT * DIN;
#pragma unroll
        for (int i = 0; i < 8; i++) {
            const int slot = i * 256 + tid;
            const int row  = slot >> 4;
            const int c    = slot & 15;
            const uint32_t dst = (uint32_t)(row * 256 + ((c ^ (row & 7)) << 4));
            cp_async16(sbase + S_B + dst, g_BT16 + bBase + (size_t)row * DIN + c * 8);
        }
    }
    CP_COMMIT();
    {
        const int slot = tid;                      // 512 chunks, 2/thread
#pragma unroll
        for (int i = 0; i < 2; i++) {
            const int s2  = i * 256 + slot;
            const int row = s2 >> 2;
            const int c   = s2 & 3;
            const uint32_t dst = (uint32_t)(row * 64 + ((c ^ ((row >> 1) & 3)) << 4));
            cp_async16(sbase + S_X + dst, g_X16 + (size_t)(m0 + row) * DIN + c * 8);
        }
    }
    CP_COMMIT();

    float acc[2][8][4];
#pragma unroll
    for (int mf = 0; mf < 2; mf++)
#pragma unroll
        for (int nf = 0; nf < 8; nf++)
#pragma unroll
            for (int q = 0; q < 4; q++) acc[mf][nf][q] = 0.f;

    const int a_row0 = wm * 32 + (lane & 15);
    const int a_ch   = lane >> 4;
    const int b_row0 = wn * 64 + (lane & 7) + ((lane >> 4) << 3);
    const int b_ch   = (lane >> 3) & 1;

#pragma unroll
    for (int kc = 0; kc < 4; kc++) {
        if (kc < 3) {
            const uint32_t xb = sbase + S_X + ((kc + 1) & 1) * XBUF;
#pragma unroll
            for (int i = 0; i < 2; i++) {
                const int s2  = i * 256 + tid;
                const int row = s2 >> 2;
                const int c   = s2 & 3;
                const uint32_t dst = (uint32_t)(row * 64 + ((c ^ ((row >> 1) & 3)) << 4));
                cp_async16(xb + dst, g_X16 + (size_t)(m0 + row) * DIN + (kc + 1) * 32 + c * 8);
            }
            CP_COMMIT();
            CP_WAIT(1);
        } else {
            CP_WAIT(0);
        }
        __syncthreads();

        const uint32_t xh = sbase + S_X + (kc & 1) * XBUF;

#pragma unroll
        for (int kfi = 0; kfi < 2; kfi++) {
            const int kf = kc * 2 + kfi;
            uint A[2][4];
#pragma unroll
            for (int mf = 0; mf < 2; mf++) {
                const int row = a_row0 + mf * 16;
                const uint32_t addr = (uint32_t)(row * 64 +
                    (((kfi * 2 + a_ch) ^ ((row >> 1) & 3)) << 4));
                ldsm_x4(A[mf], xh + addr);
            }
#pragma unroll
            for (int p = 0; p < 4; p++) {
                const int row = b_row0 + p * 16;
                const uint32_t addr = (uint32_t)(row * 256 +
                    (((kf * 2 + b_ch) ^ (row & 7)) << 4));
                uint B[4];
                ldsm_x4(B, sbase + S_B + addr);
#pragma unroll
                for (int mf = 0; mf < 2; mf++) {
                    mma_f16(acc[mf][2 * p],     A[mf], B[0], B[1]);
                    mma_f16(acc[mf][2 * p + 1], A[mf], B[2], B[3]);
                }
            }
        }
        __syncthreads();
    }

    // --- epilogue: write XB[b] fp16 ---
    __half* outBase = g_XB + (size_t)b * N_NODES * DOUT;
    const int g = lane >> 2;
    const int t2 = (lane & 3) * 2;
#pragma unroll
    for (int mf = 0; mf < 2; mf++) {
        const int r0 = m0 + wm * 32 + mf * 16 + g;
#pragma unroll
        for (int nf = 0; nf < 8; nf++) {
            const int col = wn * 64 + nf * 8 + t2;
            if (r0 < N_NODES) {
                __half2 h = __floats2half2_rn(acc[mf][nf][0], acc[mf][nf][1]);
                *(uint32_t*)(outBase + (size_t)r0 * DOUT + col) = *(uint32_t*)&h;
            }
            if (r0 + 8 < N_NODES) {
                __half2 h = __floats2half2_rn(acc[mf][nf][2], acc[mf][nf][3]);
                *(uint32_t*)(outBase + (size_t)(r0 + 8) * DOUT + col) = *(uint32_t*)&h;
            }
        }
    }
}

// ---------------------------------------------------------------------------
// FW[r][n][d] = sum_b comp[r][b] * XB[b][n][d]   (fp16 in, fp32 math, fp16 out)
// ---------------------------------------------------------------------------
__global__ __launch_bounds__(256)
void combine_kernel(const float* __restrict__ comp) {
    __shared__ float cs[R_REL * B_BASES];
    if (threadIdx.x < R_REL * B_BASES) cs[threadIdx.x] = comp[threadIdx.x];
    __syncthreads();

    const int id = blockIdx.x * blockDim.x + threadIdx.x;
    if (id >= N_NODES * 32) return;
    const int n  = id >> 5;
    const int d4 = (id & 31) * 4;

    float4 xb[8];
#pragma unroll
    for (int b = 0; b < B_BASES; b++) {
        const uint2 pk = __ldg((const uint2*)(g_XB + ((size_t)b * N_NODES + n) * DOUT + d4));
        const float2 a = __half22float2(*(const __half2*)&pk.x);
        const float2 c = __half22float2(*(const __half2*)&pk.y);
        xb[b] = make_float4(a.x, a.y, c.x, c.y);
    }

#pragma unroll
    for (int r = 0; r < R_REL; r++) {
        float4 o = make_float4(0.f, 0.f, 0.f, 0.f);
#pragma unroll
        for (int b = 0; b < B_BASES; b++) {
            const float c = cs[r * B_BASES + b];
            o.x += c * xb[b].x;
            o.y += c * xb[b].y;
            o.z += c * xb[b].z;
            o.w += c * xb[b].w;
        }
        __half2 h0 = __floats2half2_rn(o.x, o.y);
        __half2 h1 = __floats2half2_rn(o.z, o.w);
        uint2 pk;
        pk.x = *(uint32_t*)&h0;
        pk.y = *(uint32_t*)&h1;
        *(uint2*)(g_FW + ((size_t)r * N_NODES + n) * DOUT + d4) = pk;
    }
}

// ---------------------------------------------------------------------------
// Sorted scatter: one warp per output row; fp16 FW gather (8 B/lane/edge),
// unroll-4, fp32 accumulation, single non-atomic row write.
// ---------------------------------------------------------------------------
__device__ __forceinline__ float4 fw_row_f4(int col, int lane) {
    const uint2 pk = __ldg((const uint2*)(g_FW + (size_t)col * DOUT) + lane);
    const float2 a = __half22float2(*(const __half2*)&pk.x);
    const float2 b = __half22float2(*(const __half2*)&pk.y);
    return make_float4(a.x, a.y, b.x, b.y);
}

__global__ void __launch_bounds__(256)
scatter2_kernel(float* __restrict__ out) {
    const int warpId = (blockIdx.x * blockDim.x + threadIdx.x) >> 5;
    if (warpId >= N_NODES) return;
    const int lane = threadIdx.x & 31;

    const int s = g_start[warpId];
    const int e = g_start[warpId + 1];

    float4 acc = make_float4(0.f, 0.f, 0.f, 0.f);
    int i = s;
    for (; i + 4 <= e; i += 4) {
        int2 e0 = g_edge[i], e1 = g_edge[i + 1], e2 = g_edge[i + 2], e3 = g_edge[i + 3];
        float4 f0 = fw_row_f4(e0.x, lane);
        float4 f1 = fw_row_f4(e1.x, lane);
        float4 f2 = fw_row_f4(e2.x, lane);
        float4 f3 = fw_row_f4(e3.x, lane);
        const float v0 = __int_as_float(e0.y), v1 = __int_as_float(e1.y);
        const float v2 = __int_as_float(e2.y), v3 = __int_as_float(e3.y);
        acc.x += v0 * f0.x + v1 * f1.x + v2 * f2.x + v3 * f3.x;
        acc.y += v0 * f0.y + v1 * f1.y + v2 * f2.y + v3 * f3.y;
        acc.z += v0 * f0.z + v1 * f1.z + v2 * f2.z + v3 * f3.z;
        acc.w += v0 * f0.w + v1 * f1.w + v2 * f2.w + v3 * f3.w;
    }
    for (; i < e; i++) {
        int2 ed = g_edge[i];
        float4 f = fw_row_f4(ed.x, lane);
        const float v = __int_as_float(ed.y);
        acc.x += v * f.x; acc.y += v * f.y; acc.z += v * f.z; acc.w += v * f.w;
    }
    *(float4*)(out + (size_t)warpId * DOUT + lane * 4) = acc;
}

// ---------------------------------------------------------------------------
// Fork/join capture: side stream runs detect + CSR sort pipeline concurrently
// with the main GEMM chain; joins before scatter2. Stream/event creation is
// not a captured op and not a device allocation (created per call,
// deterministic; intentionally not destroyed — kernel_launch runs only for
// correctness + capture, not per replay).
// ---------------------------------------------------------------------------
extern "C" void kernel_launch(void* const* d_in, const int* in_sizes, int n_in,
                              void* d_out, int out_size) {
    const float* X      = (const float*)d_in[0];
    const void*  A_rows = d_in[1];
    const void*  A_cols = d_in[2];
    const float* A_vals = (const float*)d_in[3];
    const float* basis  = (const float*)d_in[4];
    const float* comp   = (const float*)d_in[5];
    float* out = (float*)d_out;

    cudaFuncSetAttribute(gemm_mma_kernel,
                         cudaFuncAttributeMaxDynamicSharedMemorySize, S_TOTAL);

    cudaStream_t s2;
    cudaStreamCreateWithFlags(&s2, cudaStreamNonBlocking);
    cudaEvent_t evFork, evJoin;
    cudaEventCreateWithFlags(&evFork, cudaEventDisableTiming);
    cudaEventCreateWithFlags(&evJoin, cudaEventDisableTiming);

    // fork side stream immediately (main chain does not need detect)
    cudaEventRecord(evFork, 0);
    cudaStreamWaitEvent(s2, evFork, 0);

    // side stream: dtype detect + CSR sort pipeline
    detect_dtype_kernel<<<1, 1, 0, s2>>>((const unsigned int*)A_rows);
    zero_cnt_kernel<<<(N_NODES + 255) / 256, 256, 0, s2>>>();
    hist_kernel<<<(NNZ + 255) / 256, 256, 0, s2>>>(A_rows);
    scan_kernel<<<1, 1024, 0, s2>>>();
    fill_kernel<<<(NNZ + 255) / 256, 256, 0, s2>>>(A_rows, A_cols, A_vals);
    cudaEventRecord(evJoin, s2);

    // main stream: GEMM chain
    const int px = (N_PAD * DIN) / 8;
    prep_x_kernel<<<(px + 255) / 256, 256>>>(X);
    const int pb = B_BASES * DOUT * (DIN / 4);
    prep_bt_kernel<<<(pb + 255) / 256, 256>>>(basis);

    dim3 ggrid(M_TILES, B_BASES);
    gemm_mma_kernel<<<ggrid, 256, S_TOTAL>>>(0);

    const int cthreads = N_NODES * 32;
    combine_kernel<<<(cthreads + 255) / 256, 256>>>(comp);

    // join, then final scatter
    cudaStreamWaitEvent(0, evJoin, 0);
    const long long sthreads = (long long)N_NODES * 32;
    scatter2_kernel<<<(unsigned)((sthreads + 255) / 256), 256>>>(out);
}